// round 6
// baseline (speedup 1.0000x reference)
#include <cuda_runtime.h>
#include <math.h>

#define DAYS  365
#define NY    30
#define SGRID 4000
#define TT    (DAYS * NY)
#define NPAIR 435
#define NQ    5
#define K1_SER 16

#define POSINF  __int_as_float(0x7f800000)
#define KEYINF  0x7fffffff
#define FULLM   0xffffffffu

// ---------------- intermediate storage (no allocations allowed) -------------
__device__ float  g_pM[SGRID * NY];
__device__ float  g_tM[SGRID * NY];
__device__ float  g_pQ[SGRID * NQ * NY];
__device__ float  g_tQ[SGRID * NQ * NY];
__device__ double g_sse;
__device__ double g_trend;

// monotone float<->signed-int key map (involution)
__device__ __forceinline__ int f2k(float x) {
    int b = __float_as_int(x);
    return b ^ ((b >> 31) & 0x7fffffff);
}
__device__ __forceinline__ float k2f(int k) {
    return __int_as_float(k ^ ((k >> 31) & 0x7fffffff));
}

// compile-time-direction comparators (single FMNMX / IMNMX pair each)
__device__ __forceinline__ void cswapF(float& a, float& b) {
    float lo = fminf(a, b), hi = fmaxf(a, b); a = lo; b = hi;
}
__device__ __forceinline__ void cswapI(int& a, int& b) {
    int lo = min(a, b), hi = max(a, b); a = lo; b = hi;
}

// ---------------- fused normalized bitonic sort of 512, lane-major -----------
// Sorts a float array (FMNMX/alu pipe) and an int array (IMNMX) through the
// SAME network simultaneously: dual-pipe throughput + 2x ILP.
// position g = lane*16 + r. All loops fixed-bound + guarded (regs stay regs).
__device__ __forceinline__ void bsort512f(float vF[16], int vI[16], int lane) {
    // ---- in-lane levels k = 2..16 ----
#pragma unroll
    for (int k = 2; k <= 16; k <<= 1) {
#pragma unroll
        for (int r = 0; r < 16; r++)
            if ((r & (k - 1)) < (k >> 1)) {
                cswapF(vF[r], vF[r ^ (k - 1)]);
                cswapI(vI[r], vI[r ^ (k - 1)]);
            }
#pragma unroll
        for (int j = 8; j >= 1; j >>= 1)
            if (j <= (k >> 2)) {
#pragma unroll
                for (int r = 0; r < 16; r++)
                    if ((r & j) == 0) {
                        cswapF(vF[r], vF[r | j]);
                        cswapI(vI[r], vI[r | j]);
                    }
            }
    }
    // ---- cross-lane levels k = 32..512 ----
#pragma unroll
    for (int k = 32; k <= 512; k <<= 1) {
        // flip substage: partner lane = lane ^ ((k-1)>>4), partner reg = 15-r
        {
            int  lm      = (k - 1) >> 4;
            bool keepmin = ((lane & (k >> 5)) == 0);
#pragma unroll
            for (int r = 0; r < 8; r++) {
                float aF = __shfl_xor_sync(FULLM, vF[15 - r], lm);
                float bF = __shfl_xor_sync(FULLM, vF[r], lm);
                int   aI = __shfl_xor_sync(FULLM, vI[15 - r], lm);
                int   bI = __shfl_xor_sync(FULLM, vI[r], lm);
                vF[r]      = keepmin ? fminf(vF[r], aF)      : fmaxf(vF[r], aF);
                vF[15 - r] = keepmin ? fminf(vF[15 - r], bF) : fmaxf(vF[15 - r], bF);
                vI[r]      = keepmin ? min(vI[r], aI)        : max(vI[r], aI);
                vI[15 - r] = keepmin ? min(vI[15 - r], bI)   : max(vI[15 - r], bI);
            }
        }
        // plain cross-lane substages j = k/4 .. 16
#pragma unroll
        for (int j = 128; j >= 16; j >>= 1)
            if (j <= (k >> 2)) {
                int  lm      = j >> 4;
                bool keepmin = ((lane & lm) == 0);
#pragma unroll
                for (int r = 0; r < 16; r++) {
                    float oF = __shfl_xor_sync(FULLM, vF[r], lm);
                    int   oI = __shfl_xor_sync(FULLM, vI[r], lm);
                    vF[r] = keepmin ? fminf(vF[r], oF) : fmaxf(vF[r], oF);
                    vI[r] = keepmin ? min(vI[r], oI)   : max(vI[r], oI);
                }
            }
        // plain in-lane substages j = 8..1
#pragma unroll
        for (int j = 8; j >= 1; j >>= 1) {
#pragma unroll
            for (int r = 0; r < 16; r++)
                if ((r & j) == 0) {
                    cswapF(vF[r], vF[r | j]);
                    cswapI(vI[r], vI[r | j]);
                }
        }
    }
}

// ---------------- kernel 0: zero accumulators --------------------------------
__global__ void k_zero() {
    g_sse = 0.0;
    g_trend = 0.0;
}

// ---------------- kernel 1: transpose + SSE + fused P/T sort ----------------
// grid (SGRID/K1_SER, NY), block 512 (16 warps, 1 warp per series)
__global__ __launch_bounds__(512) void k_sortdays(const float* __restrict__ pred,
                                                  const float* __restrict__ obs) {
    __shared__ float shP[K1_SER][DAYS];
    __shared__ float shT[K1_SER][DAYS];
    __shared__ float warpsum[16];

    int y      = blockIdx.y;
    int s_base = blockIdx.x * K1_SER;
    int tid    = threadIdx.x;
    int w      = tid >> 5;
    int lane   = tid & 31;

    const float* pbase = pred + y * DAYS * SGRID + s_base;
    const float* tbase = obs  + y * DAYS * SGRID + s_base;

    // coalesced load + transpose + fused SSE
    float sse = 0.0f;
    for (int idx = tid; idx < DAYS * K1_SER; idx += 512) {
        int d  = idx >> 4;
        int sl = idx & 15;
        float a = pbase[d * SGRID + sl];
        float b = tbase[d * SGRID + sl];
        shP[sl][d] = a;
        shT[sl][d] = b;
        float df = a - b;
        sse += df * df;
    }
#pragma unroll
    for (int o = 16; o > 0; o >>= 1) sse += __shfl_down_sync(FULLM, sse, o);
    if (lane == 0) warpsum[w] = sse;
    __syncthreads();
    if (tid == 0) {
        float tot = 0.0f;
#pragma unroll
        for (int i = 0; i < 16; i++) tot += warpsum[i];
        atomicAdd(&g_sse, (double)tot);
    }

    int s = s_base + w;

    // one fused pass: P as floats, T as monotone int keys
    float vF[16];
    int   vI[16];
    float msP = 0.0f, msT = 0.0f;
#pragma unroll
    for (int r = 0; r < 16; r++) {
        int g = (r << 5) | lane;        // arbitrary slot permutation (set-invariant)
        if (g < DAYS) {
            float a = shP[w][g];
            float b = shT[w][g];
            msP += a; msT += b;
            vF[r] = a;
            vI[r] = f2k(b);
        } else {
            vF[r] = POSINF;
            vI[r] = KEYINF;
        }
    }
#pragma unroll
    for (int o = 16; o > 0; o >>= 1) {
        msP += __shfl_down_sync(FULLM, msP, o);
        msT += __shfl_down_sync(FULLM, msT, o);
    }
    if (lane == 0) {
        g_pM[s * NY + y] = msP / (float)DAYS;
        g_tM[s * NY + y] = msT / (float)DAYS;
    }

    bsort512f(vF, vI, lane);

    // order statistics (lane-major): rank g -> lane g>>4, reg g&15
    if (lane == 22) {
        g_pQ[(s * NQ + 0) * NY + y] = vF[12];        // g=364
        g_tQ[(s * NQ + 0) * NY + y] = k2f(vI[12]);
        g_pQ[(s * NQ + 1) * NY + y] = vF[5];         // g=357
        g_tQ[(s * NQ + 1) * NY + y] = k2f(vI[5]);
    }
    if (lane == 11) {
        g_pQ[(s * NQ + 2) * NY + y] = vF[6];         // g=182
        g_tQ[(s * NQ + 2) * NY + y] = k2f(vI[6]);
    }
    if (lane == 6) {
        g_pQ[(s * NQ + 3) * NY + y] = vF[13];        // g=109
        g_tQ[(s * NQ + 3) * NY + y] = k2f(vI[13]);
    }
    if (lane == 0) {
        g_pQ[(s * NQ + 4) * NY + y] = vF[7];         // g=7
        g_tQ[(s * NQ + 4) * NY + y] = k2f(vI[7]);
    }
}

// ---------------- kernel 2: Theil-Sen medians + trend terms ------------------
// grid SGRID, block 192 (6 warps: warp0 = mean, warps 1..5 = quantiles)
__global__ __launch_bounds__(192) void k_theil() {
    __shared__ float xs[6][2][NY];

    int s    = blockIdx.x;
    int w    = threadIdx.x >> 5;
    int lane = threadIdx.x & 31;

    const float* xp;
    const float* xt;
    if (w == 0) { xp = g_pM + s * NY;                  xt = g_tM + s * NY; }
    else        { xp = g_pQ + (s * NQ + (w - 1)) * NY; xt = g_tQ + (s * NQ + (w - 1)) * NY; }
    if (lane < NY) {
        xs[w][0][lane] = xp[lane];
        xs[w][1][lane] = xt[lane];
    }
    __syncwarp();

    float vF[16];   // pred slopes as floats
    int   vI[16];   // targ slopes as int keys
#pragma unroll
    for (int r = 0; r < 16; r++) {
        int p = (r << 5) | lane;   // arbitrary pair->slot map (median is set-invariant)
        if (p < NPAIR) {
            int i = 0, rem = p, cnt = NY - 1;
            while (rem >= cnt) { rem -= cnt; i++; cnt--; }
            int j = i + 1 + rem;
            float denom = (float)(j - i);
            vF[r] = (xs[w][0][j] - xs[w][0][i]) / denom;
            vI[r] = f2k((xs[w][1][j] - xs[w][1][i]) / denom);
        } else {
            vF[r] = POSINF;
            vI[r] = KEYINF;
        }
    }

    bsort512f(vF, vI, lane);

    // median of 435 = sorted element 217 -> lane 13, reg 9
    float sp = __shfl_sync(FULLM, vF[9], 13);
    int   ki = __shfl_sync(FULLM, vI[9], 13);

    if (lane == 0) {
        float st = k2f(ki);
        double term;
        if (w == 0) { float d = st - sp;   term = (double)d * (double)d; }
        else        { float q = st / (-sp); term = (double)q * (double)q; }
        atomicAdd(&g_trend, term);
    }
}

// ---------------- kernel 3: finalize -----------------------------------------
__global__ void k_final(float* out) {
    double mse = g_sse / ((double)TT * (double)SGRID);
    out[0] = (float)(sqrt(mse) + g_trend / (double)SGRID);
}

// ---------------- launch ------------------------------------------------------
extern "C" void kernel_launch(void* const* d_in, const int* in_sizes, int n_in,
                              void* d_out, int out_size) {
    const float* y_pred = (const float*)d_in[0];
    const float* y_obs  = (const float*)d_in[1];
    float* out = (float*)d_out;

    k_zero<<<1, 1>>>();
    k_sortdays<<<dim3(SGRID / K1_SER, NY), 512>>>(y_pred, y_obs);
    k_theil<<<SGRID, 192>>>();
    k_final<<<1, 1>>>(out);
}

// round 7
// speedup vs baseline: 1.2207x; 1.2207x over previous
#include <cuda_runtime.h>
#include <math.h>

#define DAYS  365
#define NY    30
#define SGRID 4000
#define TT    (DAYS * NY)
#define NPAIR 435
#define NQ    5
#define K1_SER 16
#define SROW  369            // smem row stride (floats); 368 needed, odd-ish mod 32

#define POSINF __int_as_float(0x7f800000)
#define FULLM  0xffffffffu

// ---------------- intermediate storage (no allocations allowed) -------------
__device__ float  g_pM[SGRID * NY];
__device__ float  g_tM[SGRID * NY];
__device__ float  g_pQ[SGRID * NQ * NY];
__device__ float  g_tQ[SGRID * NQ * NY];
__device__ double g_sse;
__device__ double g_trend;

// compile-time-direction comparator: a <- min, b <- max (2 FMNMX)
__device__ __forceinline__ void cswapF(float& a, float& b) {
    float lo = fminf(a, b), hi = fmaxf(a, b); a = lo; b = hi;
}

// ======================= 384-slot pruned bitonic sorter ======================
// Slot index g (0..511): bits {g1,g0} -> reg low 2 bits, {g8,g7} -> reg high
// 2 bits (hi2), {g6..g2} -> lane. r = (g&3) | ((g>>7)<<2). Virtual slots are
// g>=384 <=> r>=12: never materialized (they hold +INF throughout in the
// normalized min-down network, so all their comparators are pruned).
// 528 FMNMX + 316 SHFL per sort vs 720/240 for the full 512 network.

__device__ __forceinline__ void inreg_x1(float v[12]) {   // stride g0 (j=1)
    cswapF(v[0],v[1]);  cswapF(v[2],v[3]);  cswapF(v[4],v[5]);
    cswapF(v[6],v[7]);  cswapF(v[8],v[9]);  cswapF(v[10],v[11]);
}
__device__ __forceinline__ void inreg_x2(float v[12]) {   // stride g1 (j=2)
    cswapF(v[0],v[2]);  cswapF(v[1],v[3]);  cswapF(v[4],v[6]);
    cswapF(v[5],v[7]);  cswapF(v[8],v[10]); cswapF(v[9],v[11]);
}
__device__ __forceinline__ void inreg_x3(float v[12]) {   // flip k=4 (r^3)
    cswapF(v[0],v[3]);  cswapF(v[1],v[2]);  cswapF(v[4],v[7]);
    cswapF(v[5],v[6]);  cswapF(v[8],v[11]); cswapF(v[9],v[10]);
}
__device__ __forceinline__ void inreg_p128(float v[12]) { // stride g7 (j=128), hi2 0<->1
    cswapF(v[0],v[4]);  cswapF(v[1],v[5]);  cswapF(v[2],v[6]);  cswapF(v[3],v[7]);
}

// plain cross-lane substage, lane mask lm (global stride j = 4*lm)
__device__ __forceinline__ void cross_plain(float v[12], int lane, int lm) {
    bool kp = (lane & lm) == 0;
#pragma unroll
    for (int r = 0; r < 12; r++) {
        float o = __shfl_xor_sync(FULLM, v[r], lm);
        v[r] = kp ? fminf(v[r], o) : fmaxf(v[r], o);
    }
}

// flip substage for k = 8..128: lane complement mask lmc, reg partner r^3,
// this slot keeps min iff (lane & pb)==0 (pb = top lane bit of the block)
__device__ __forceinline__ void flip_c(float v[12], int lane, int lmc, int pb) {
    bool kp = (lane & pb) == 0;
    float t[12];
#pragma unroll
    for (int r = 0; r < 12; r++) t[r] = __shfl_xor_sync(FULLM, v[r ^ 3], lmc);
#pragma unroll
    for (int r = 0; r < 12; r++) v[r] = kp ? fminf(v[r], t[r]) : fmaxf(v[r], t[r]);
}

// flip k=256: partner r^7, lane^31. Kept pairs (0,7),(1,6),(2,5),(3,4);
// hi2=2 partners are virtual (pruned). Direction compile-time (g7 is reg bit).
__device__ __forceinline__ void flip256(float v[12], int lane) {
    float t0 = __shfl_xor_sync(FULLM, v[7], 31);
    float t1 = __shfl_xor_sync(FULLM, v[6], 31);
    float t2 = __shfl_xor_sync(FULLM, v[5], 31);
    float t3 = __shfl_xor_sync(FULLM, v[4], 31);
    float u0 = __shfl_xor_sync(FULLM, v[0], 31);
    float u1 = __shfl_xor_sync(FULLM, v[1], 31);
    float u2 = __shfl_xor_sync(FULLM, v[2], 31);
    float u3 = __shfl_xor_sync(FULLM, v[3], 31);
    v[0] = fminf(v[0], t0); v[1] = fminf(v[1], t1);
    v[2] = fminf(v[2], t2); v[3] = fminf(v[3], t3);
    v[7] = fmaxf(v[7], u0); v[6] = fmaxf(v[6], u1);
    v[5] = fmaxf(v[5], u2); v[4] = fmaxf(v[4], u3);
}

// flip k=512: partner r^15, lane^31. Kept pairs (4,11),(5,10),(6,9),(7,8);
// r=0..3 partners are virtual (pruned). Direction compile-time (g8 is reg bit).
__device__ __forceinline__ void flip512(float v[12], int lane) {
    float t0 = __shfl_xor_sync(FULLM, v[11], 31);
    float t1 = __shfl_xor_sync(FULLM, v[10], 31);
    float t2 = __shfl_xor_sync(FULLM, v[9], 31);
    float t3 = __shfl_xor_sync(FULLM, v[8], 31);
    float u0 = __shfl_xor_sync(FULLM, v[4], 31);
    float u1 = __shfl_xor_sync(FULLM, v[5], 31);
    float u2 = __shfl_xor_sync(FULLM, v[6], 31);
    float u3 = __shfl_xor_sync(FULLM, v[7], 31);
    v[4]  = fminf(v[4], t0);  v[5]  = fminf(v[5], t1);
    v[6]  = fminf(v[6], t2);  v[7]  = fminf(v[7], t3);
    v[11] = fmaxf(v[11], u0); v[10] = fmaxf(v[10], u1);
    v[9]  = fmaxf(v[9], u2);  v[8]  = fmaxf(v[8], u3);
}

__device__ __forceinline__ void bsort384(float v[12], int lane) {
    inreg_x1(v);                                                    // k=2
    inreg_x3(v); inreg_x1(v);                                       // k=4
    flip_c(v, lane, 1, 1);  inreg_x2(v); inreg_x1(v);               // k=8
    flip_c(v, lane, 3, 2);  cross_plain(v, lane, 1);
    inreg_x2(v); inreg_x1(v);                                       // k=16
    flip_c(v, lane, 7, 4);  cross_plain(v, lane, 2);  cross_plain(v, lane, 1);
    inreg_x2(v); inreg_x1(v);                                       // k=32
    flip_c(v, lane, 15, 8); cross_plain(v, lane, 4);  cross_plain(v, lane, 2);
    cross_plain(v, lane, 1); inreg_x2(v); inreg_x1(v);              // k=64
    flip_c(v, lane, 31, 16); cross_plain(v, lane, 8); cross_plain(v, lane, 4);
    cross_plain(v, lane, 2); cross_plain(v, lane, 1);
    inreg_x2(v); inreg_x1(v);                                       // k=128
    flip256(v, lane); cross_plain(v, lane, 16); cross_plain(v, lane, 8);
    cross_plain(v, lane, 4); cross_plain(v, lane, 2); cross_plain(v, lane, 1);
    inreg_x2(v); inreg_x1(v);                                       // k=256
    flip512(v, lane); inreg_p128(v); cross_plain(v, lane, 16);
    cross_plain(v, lane, 8); cross_plain(v, lane, 4); cross_plain(v, lane, 2);
    cross_plain(v, lane, 1); inreg_x2(v); inreg_x1(v);              // k=512
}

// ================= full 512 sorter (lane-major, for k_theil) =================
__device__ __forceinline__ void bsort512(float v[16], int lane) {
#pragma unroll
    for (int k = 2; k <= 16; k <<= 1) {
#pragma unroll
        for (int r = 0; r < 16; r++)
            if ((r & (k - 1)) < (k >> 1)) cswapF(v[r], v[r ^ (k - 1)]);
#pragma unroll
        for (int j = 8; j >= 1; j >>= 1)
            if (j <= (k >> 2)) {
#pragma unroll
                for (int r = 0; r < 16; r++)
                    if ((r & j) == 0) cswapF(v[r], v[r | j]);
            }
    }
#pragma unroll
    for (int k = 32; k <= 512; k <<= 1) {
        {
            int  lm      = (k - 1) >> 4;
            bool keepmin = ((lane & (k >> 5)) == 0);
#pragma unroll
            for (int r = 0; r < 8; r++) {
                float a = __shfl_xor_sync(FULLM, v[15 - r], lm);
                float b = __shfl_xor_sync(FULLM, v[r], lm);
                v[r]      = keepmin ? fminf(v[r], a)      : fmaxf(v[r], a);
                v[15 - r] = keepmin ? fminf(v[15 - r], b) : fmaxf(v[15 - r], b);
            }
        }
#pragma unroll
        for (int j = 128; j >= 16; j >>= 1)
            if (j <= (k >> 2)) {
                int  lm      = j >> 4;
                bool keepmin = ((lane & lm) == 0);
#pragma unroll
                for (int r = 0; r < 16; r++) {
                    float o = __shfl_xor_sync(FULLM, v[r], lm);
                    v[r] = keepmin ? fminf(v[r], o) : fmaxf(v[r], o);
                }
            }
#pragma unroll
        for (int j = 8; j >= 1; j >>= 1) {
#pragma unroll
            for (int r = 0; r < 16; r++)
                if ((r & j) == 0) cswapF(v[r], v[r | j]);
        }
    }
}

// ---------------- kernel 0: zero accumulators --------------------------------
__global__ void k_zero() {
    g_sse = 0.0;
    g_trend = 0.0;
}

// ---------------- kernel 1: transpose + SSE + per-(series,year) sort ---------
// grid (SGRID/K1_SER, NY), block 512 (16 warps, 1 warp per series)
__global__ __launch_bounds__(512) void k_sortdays(const float* __restrict__ pred,
                                                  const float* __restrict__ obs) {
    __shared__ float shP[K1_SER][SROW];
    __shared__ float shT[K1_SER][SROW];
    __shared__ float warpsum[16];

    int y      = blockIdx.y;
    int s_base = blockIdx.x * K1_SER;
    int tid    = threadIdx.x;
    int w      = tid >> 5;
    int lane   = tid & 31;

    const float* pbase = pred + y * DAYS * SGRID + s_base;
    const float* tbase = obs  + y * DAYS * SGRID + s_base;

    // coalesced load + transpose (day d -> smem addr (d&3)*92 + (d>>2)) + SSE
    float sse = 0.0f;
    for (int idx = tid; idx < DAYS * K1_SER; idx += 512) {
        int d  = idx >> 4;
        int sl = idx & 15;
        int ad = (d & 3) * 92 + (d >> 2);
        float a = pbase[d * SGRID + sl];
        float b = tbase[d * SGRID + sl];
        shP[sl][ad] = a;
        shT[sl][ad] = b;
        float df = a - b;
        sse += df * df;
    }
#pragma unroll
    for (int o = 16; o > 0; o >>= 1) sse += __shfl_down_sync(FULLM, sse, o);
    if (lane == 0) warpsum[w] = sse;
    __syncthreads();
    if (tid == 0) {
        float tot = 0.0f;
#pragma unroll
        for (int i = 0; i < 16; i++) tot += warpsum[i];
        atomicAdd(&g_sse, (double)tot);
    }

    int s = s_base + w;

#pragma unroll 1
    for (int pass = 0; pass < 2; pass++) {
        float (*sh)[SROW] = pass ? shT : shP;
        float* outM = pass ? g_tM : g_pM;
        float* outQ = pass ? g_tQ : g_pQ;

        // load slots: reg r holds slot g = (r&3) + 4*lane + 128*(r>>2)
        float v[12];
        float msum = 0.0f;
#pragma unroll
        for (int r = 0; r < 12; r++) {
            int lo2 = r & 3;
            int pos = lane + 32 * (r >> 2);
            int g   = lo2 + 4 * pos;
            if (g < DAYS) { v[r] = sh[w][lo2 * 92 + pos]; msum += v[r]; }
            else          { v[r] = POSINF; }
        }
        // yearly mean
#pragma unroll
        for (int o = 16; o > 0; o >>= 1) msum += __shfl_down_sync(FULLM, msum, o);
        if (lane == 0) outM[s * NY + y] = msum / (float)DAYS;

        bsort384(v, lane);

        // rank R -> reg (R&3)|((R>>7)<<2), lane (R>>2)&31
        if (lane == 27) {
            outQ[(s * NQ + 0) * NY + y] = v[8];   // rank 364
            outQ[(s * NQ + 3) * NY + y] = v[1];   // rank 109
        }
        if (lane == 25) outQ[(s * NQ + 1) * NY + y] = v[9];   // rank 357
        if (lane == 13) outQ[(s * NQ + 2) * NY + y] = v[6];   // rank 182
        if (lane == 1)  outQ[(s * NQ + 4) * NY + y] = v[3];   // rank 7
    }
}

// ---------------- kernel 2: Theil-Sen medians + trend terms ------------------
// grid SGRID, block 192 (6 warps: warp0 = mean, warps 1..5 = quantiles)
__global__ __launch_bounds__(192) void k_theil() {
    __shared__ float xs[6][2][NY];

    int s    = blockIdx.x;
    int w    = threadIdx.x >> 5;
    int lane = threadIdx.x & 31;

    const float* xp;
    const float* xt;
    if (w == 0) { xp = g_pM + s * NY;                  xt = g_tM + s * NY; }
    else        { xp = g_pQ + (s * NQ + (w - 1)) * NY; xt = g_tQ + (s * NQ + (w - 1)) * NY; }
    if (lane < NY) {
        xs[w][0][lane] = xp[lane];
        xs[w][1][lane] = xt[lane];
    }
    __syncwarp();

    float med[2];
#pragma unroll 1
    for (int pass = 0; pass < 2; pass++) {
        float v[16];
#pragma unroll
        for (int r = 0; r < 16; r++) {
            int p = (r << 5) | lane;   // arbitrary pair->slot map (median is set-invariant)
            if (p < NPAIR) {
                int i = 0, rem = p, cnt = NY - 1;
                while (rem >= cnt) { rem -= cnt; i++; cnt--; }
                int j = i + 1 + rem;
                v[r] = (xs[w][pass][j] - xs[w][pass][i]) / (float)(j - i);
            } else {
                v[r] = POSINF;
            }
        }
        bsort512(v, lane);
        // median of 435 = sorted element 217 -> lane 13, reg 9 (lane-major)
        med[pass] = __shfl_sync(FULLM, v[9], 13);
    }

    if (lane == 0) {
        float sp = med[0], st = med[1];
        double term;
        if (w == 0) { float d = st - sp;   term = (double)d * (double)d; }
        else        { float q = st / (-sp); term = (double)q * (double)q; }
        atomicAdd(&g_trend, term);
    }
}

// ---------------- kernel 3: finalize -----------------------------------------
__global__ void k_final(float* out) {
    double mse = g_sse / ((double)TT * (double)SGRID);
    out[0] = (float)(sqrt(mse) + g_trend / (double)SGRID);
}

// ---------------- launch ------------------------------------------------------
extern "C" void kernel_launch(void* const* d_in, const int* in_sizes, int n_in,
                              void* d_out, int out_size) {
    const float* y_pred = (const float*)d_in[0];
    const float* y_obs  = (const float*)d_in[1];
    float* out = (float*)d_out;

    k_zero<<<1, 1>>>();
    k_sortdays<<<dim3(SGRID / K1_SER, NY), 512>>>(y_pred, y_obs);
    k_theil<<<SGRID, 192>>>();
    k_final<<<1, 1>>>(out);
}

// round 8
// speedup vs baseline: 1.5160x; 1.2419x over previous
#include <cuda_runtime.h>
#include <math.h>

#define DAYS  365
#define NY    30
#define SGRID 4000
#define TT    (DAYS * NY)
#define NPAIR 435
#define NQ    5
#define K1_SER 16
#define SROW  369            // smem row stride (floats); row needs 368

#define POSINF __int_as_float(0x7f800000)
#define FULLM  0xffffffffu

// ---------------- intermediate storage (no allocations allowed) -------------
__device__ float  g_pM[SGRID * NY];
__device__ float  g_tM[SGRID * NY];
__device__ float  g_pQ[SGRID * NQ * NY];
__device__ float  g_tQ[SGRID * NQ * NY];
__device__ double g_sse;
__device__ double g_trend;
__device__ int    g_pairIJ[NPAIR];   // i | (j<<8)
__device__ float  g_pairInv[NPAIR];  // 1/(j-i)

// compile-time-direction comparator: a <- min, b <- max (2 FMNMX)
__device__ __forceinline__ void cswapF(float& a, float& b) {
    float lo = fminf(a, b), hi = fmaxf(a, b); a = lo; b = hi;
}

// ============ 384-slot pruned bitonic, 24 regs, TWO series per warp ==========
// Slot g (9 bits): {g0,g1,g2} -> reg lo3, {g3..g6} -> lane4 (lane&15),
// {g7,g8} -> reg hi2 (hi2==3 virtual/pruned). r = lo3 | (hi2<<3), 0..23.
// lane bit 4 selects which of the two series this half-warp sorts.
// Normalized (min-to-lower-index) network; +INF padding stays in virtual
// slots so all their comparators are pruned. 528 FMNMX + 232 SHFL per sort.

__device__ __forceinline__ void P1(float v[24]) {
#pragma unroll
    for (int r = 0; r < 24; r++) if ((r & 1) == 0) cswapF(v[r], v[r | 1]);
}
__device__ __forceinline__ void P2(float v[24]) {
#pragma unroll
    for (int r = 0; r < 24; r++) if ((r & 2) == 0) cswapF(v[r], v[r | 2]);
}
__device__ __forceinline__ void P4(float v[24]) {
#pragma unroll
    for (int r = 0; r < 24; r++) if ((r & 4) == 0) cswapF(v[r], v[r | 4]);
}
__device__ __forceinline__ void F3(float v[24]) {
#pragma unroll
    for (int r = 0; r < 24; r++) if ((r & 3) < 2) cswapF(v[r], v[r ^ 3]);
}
__device__ __forceinline__ void F7(float v[24]) {
#pragma unroll
    for (int r = 0; r < 24; r++) if ((r & 7) < 4) cswapF(v[r], v[r ^ 7]);
}
__device__ __forceinline__ void P128(float v[24]) {   // hi2 0<->1; 2<->3 pruned
#pragma unroll
    for (int r = 0; r < 8; r++) cswapF(v[r], v[r + 8]);
}
// plain cross-lane substage: global stride 8*lm, lm in {1,2,4,8}
__device__ __forceinline__ void CR(float v[24], int lane, int lm) {
    bool kp = (lane & lm) == 0;
#pragma unroll
    for (int r = 0; r < 24; r++) {
        float o = __shfl_xor_sync(FULLM, v[r], lm);
        v[r] = kp ? fminf(v[r], o) : fmaxf(v[r], o);
    }
}
// flip substage for k=16..128: lane complement lmc, reg partner lo3^7,
// direction lane bit pb (top bit of the block)
__device__ __forceinline__ void FL(float v[24], int lane, int lmc, int pb) {
    bool kp = (lane & pb) == 0;
    float t[24];
#pragma unroll
    for (int r = 0; r < 24; r++) t[r] = __shfl_xor_sync(FULLM, v[r ^ 7], lmc);
#pragma unroll
    for (int r = 0; r < 24; r++) v[r] = kp ? fminf(v[r], t[r]) : fmaxf(v[r], t[r]);
}
// flip k=256: pairs hi2 0<->1 (reg r^15), lane^15; hi2=2 pruned (vs virtual)
__device__ __forceinline__ void F256(float v[24]) {
    float t[16];
#pragma unroll
    for (int r = 0; r < 16; r++) t[r] = __shfl_xor_sync(FULLM, v[r ^ 15], 15);
#pragma unroll
    for (int r = 0; r < 8; r++)  v[r] = fminf(v[r], t[r]);
#pragma unroll
    for (int r = 8; r < 16; r++) v[r] = fmaxf(v[r], t[r]);
}
// flip k=512: pairs hi2 1<->2 (reg r^31), lane^15; hi2=0 pruned (vs virtual)
__device__ __forceinline__ void F512(float v[24]) {
    float t[16];
#pragma unroll
    for (int r = 8; r < 24; r++) t[r - 8] = __shfl_xor_sync(FULLM, v[r ^ 31], 15);
#pragma unroll
    for (int r = 8; r < 16; r++)  v[r] = fminf(v[r], t[r - 8]);
#pragma unroll
    for (int r = 16; r < 24; r++) v[r] = fmaxf(v[r], t[r - 8]);
}

__device__ __forceinline__ void bsort384h(float v[24], int lane) {
    P1(v);                                                   // k=2
    F3(v); P1(v);                                            // k=4
    F7(v); P2(v); P1(v);                                     // k=8
    FL(v, lane, 1, 1);  P4(v); P2(v); P1(v);                 // k=16
    FL(v, lane, 3, 2);  CR(v, lane, 1); P4(v); P2(v); P1(v); // k=32
    FL(v, lane, 7, 4);  CR(v, lane, 2); CR(v, lane, 1);
    P4(v); P2(v); P1(v);                                     // k=64
    FL(v, lane, 15, 8); CR(v, lane, 4); CR(v, lane, 2); CR(v, lane, 1);
    P4(v); P2(v); P1(v);                                     // k=128
    F256(v); CR(v, lane, 8); CR(v, lane, 4); CR(v, lane, 2); CR(v, lane, 1);
    P4(v); P2(v); P1(v);                                     // k=256
    F512(v); P128(v); CR(v, lane, 8); CR(v, lane, 4); CR(v, lane, 2);
    CR(v, lane, 1); P4(v); P2(v); P1(v);                     // k=512
}

// ================= full 512 sorter (lane-major, for k_theil) =================
__device__ __forceinline__ void bsort512(float v[16], int lane) {
#pragma unroll
    for (int k = 2; k <= 16; k <<= 1) {
#pragma unroll
        for (int r = 0; r < 16; r++)
            if ((r & (k - 1)) < (k >> 1)) cswapF(v[r], v[r ^ (k - 1)]);
#pragma unroll
        for (int j = 8; j >= 1; j >>= 1)
            if (j <= (k >> 2)) {
#pragma unroll
                for (int r = 0; r < 16; r++)
                    if ((r & j) == 0) cswapF(v[r], v[r | j]);
            }
    }
#pragma unroll
    for (int k = 32; k <= 512; k <<= 1) {
        {
            int  lm      = (k - 1) >> 4;
            bool keepmin = ((lane & (k >> 5)) == 0);
#pragma unroll
            for (int r = 0; r < 8; r++) {
                float a = __shfl_xor_sync(FULLM, v[15 - r], lm);
                float b = __shfl_xor_sync(FULLM, v[r], lm);
                v[r]      = keepmin ? fminf(v[r], a)      : fmaxf(v[r], a);
                v[15 - r] = keepmin ? fminf(v[15 - r], b) : fmaxf(v[15 - r], b);
            }
        }
#pragma unroll
        for (int j = 128; j >= 16; j >>= 1)
            if (j <= (k >> 2)) {
                int  lm      = j >> 4;
                bool keepmin = ((lane & lm) == 0);
#pragma unroll
                for (int r = 0; r < 16; r++) {
                    float o = __shfl_xor_sync(FULLM, v[r], lm);
                    v[r] = keepmin ? fminf(v[r], o) : fmaxf(v[r], o);
                }
            }
#pragma unroll
        for (int j = 8; j >= 1; j >>= 1) {
#pragma unroll
            for (int r = 0; r < 16; r++)
                if ((r & j) == 0) cswapF(v[r], v[r | j]);
        }
    }
}

// ---------------- kernel 0: zero accumulators + build pair tables ------------
__global__ void k_zero() {
    int tid = threadIdx.x;
    if (tid == 0) { g_sse = 0.0; g_trend = 0.0; }
    if (tid < NPAIR) {
        int i = 0, rem = tid, cnt = NY - 1;
        while (rem >= cnt) { rem -= cnt; i++; cnt--; }
        int j = i + 1 + rem;
        g_pairIJ[tid]  = i | (j << 8);
        g_pairInv[tid] = 1.0f / (float)(j - i);
    }
}

// ---------------- kernel 1: transpose + SSE + per-(series,year) sort ---------
// grid (SGRID/16, NY), block 256 (8 warps; each warp sorts 2 series per pass)
__global__ __launch_bounds__(256) void k_sortdays(const float* __restrict__ pred,
                                                  const float* __restrict__ obs) {
    __shared__ float shP[K1_SER][SROW];
    __shared__ float shT[K1_SER][SROW];
    __shared__ float warpsum[8];

    int y      = blockIdx.y;
    int s_base = blockIdx.x * K1_SER;
    int tid    = threadIdx.x;
    int w      = tid >> 5;
    int lane   = tid & 31;
    int lane4  = lane & 15;

    const float* pbase = pred + y * DAYS * SGRID + s_base;
    const float* tbase = obs  + y * DAYS * SGRID + s_base;

    // coalesced load + transpose (day d -> addr (d&7)*46 + (d>>3)) + fused SSE
    float sse = 0.0f;
    for (int idx = tid; idx < DAYS * K1_SER; idx += 256) {
        int d  = idx >> 4;
        int sl = idx & 15;
        int ad = (d & 7) * 46 + (d >> 3);
        float a = pbase[d * SGRID + sl];
        float b = tbase[d * SGRID + sl];
        shP[sl][ad] = a;
        shT[sl][ad] = b;
        float df = a - b;
        sse += df * df;
    }
#pragma unroll
    for (int o = 16; o > 0; o >>= 1) sse += __shfl_down_sync(FULLM, sse, o);
    if (lane == 0) warpsum[w] = sse;
    __syncthreads();
    if (tid == 0) {
        float tot = 0.0f;
#pragma unroll
        for (int i = 0; i < 8; i++) tot += warpsum[i];
        atomicAdd(&g_sse, (double)tot);
    }

    // this half-warp's series
    int sidx = 2 * w + (lane >> 4);     // 0..15 within block
    int s    = s_base + sidx;

#pragma unroll 1
    for (int pass = 0; pass < 2; pass++) {
        float (*sh)[SROW] = pass ? shT : shP;
        float* outM = pass ? g_tM : g_pM;
        float* outQ = pass ? g_tQ : g_pQ;

        // load: reg r holds slot g = (r&7) | (lane4<<3) | ((r>>3)<<7)
        float v[24];
        float msum = 0.0f;
#pragma unroll
        for (int r = 0; r < 24; r++) {
            int lo3 = r & 7, hi2 = r >> 3;
            int g   = lo3 | (lane4 << 3) | (hi2 << 7);
            if (g < DAYS) { v[r] = sh[sidx][lo3 * 46 + lane4 + (hi2 << 4)]; msum += v[r]; }
            else          { v[r] = POSINF; }
        }
        // per-half mean (xor butterfly within 16-lane half)
#pragma unroll
        for (int o = 8; o > 0; o >>= 1) msum += __shfl_xor_sync(FULLM, msum, o);
        if (lane4 == 0) outM[s * NY + y] = msum / (float)DAYS;

        bsort384h(v, lane);

        // rank R -> reg (R&7)|((R>>7)<<3), lane4 (R>>3)&15
        if (lane4 == 13) {
            outQ[(s * NQ + 0) * NY + y] = v[20];  // rank 364
            outQ[(s * NQ + 3) * NY + y] = v[5];   // rank 109
        }
        if (lane4 == 12) outQ[(s * NQ + 1) * NY + y] = v[21];  // rank 357
        if (lane4 == 6)  outQ[(s * NQ + 2) * NY + y] = v[14];  // rank 182
        if (lane4 == 0)  outQ[(s * NQ + 4) * NY + y] = v[7];   // rank 7
    }
}

// ---------------- kernel 2: Theil-Sen medians + trend terms ------------------
// grid SGRID, block 192 (6 warps: warp0 = mean, warps 1..5 = quantiles)
__global__ __launch_bounds__(192) void k_theil() {
    __shared__ float xs[6][2][NY];

    int s    = blockIdx.x;
    int w    = threadIdx.x >> 5;
    int lane = threadIdx.x & 31;

    const float* xp;
    const float* xt;
    if (w == 0) { xp = g_pM + s * NY;                  xt = g_tM + s * NY; }
    else        { xp = g_pQ + (s * NQ + (w - 1)) * NY; xt = g_tQ + (s * NQ + (w - 1)) * NY; }
    if (lane < NY) {
        xs[w][0][lane] = xp[lane];
        xs[w][1][lane] = xt[lane];
    }
    __syncwarp();

    float med[2];
#pragma unroll 1
    for (int pass = 0; pass < 2; pass++) {
        float v[16];
#pragma unroll
        for (int r = 0; r < 16; r++) {
            int p = (r << 5) | lane;   // arbitrary pair->slot map (median is set-invariant)
            if (p < NPAIR) {
                int   ij  = g_pairIJ[p];
                float inv = g_pairInv[p];
                int i = ij & 255, j = ij >> 8;
                v[r] = (xs[w][pass][j] - xs[w][pass][i]) * inv;
            } else {
                v[r] = POSINF;
            }
        }
        bsort512(v, lane);
        // median of 435 = sorted element 217 -> lane 13, reg 9 (lane-major)
        med[pass] = __shfl_sync(FULLM, v[9], 13);
    }

    if (lane == 0) {
        float sp = med[0], st = med[1];
        double term;
        if (w == 0) { float d = st - sp;   term = (double)d * (double)d; }
        else        { float q = st / (-sp); term = (double)q * (double)q; }
        atomicAdd(&g_trend, term);
    }
}

// ---------------- kernel 3: finalize -----------------------------------------
__global__ void k_final(float* out) {
    double mse = g_sse / ((double)TT * (double)SGRID);
    out[0] = (float)(sqrt(mse) + g_trend / (double)SGRID);
}

// ---------------- launch ------------------------------------------------------
extern "C" void kernel_launch(void* const* d_in, const int* in_sizes, int n_in,
                              void* d_out, int out_size) {
    const float* y_pred = (const float*)d_in[0];
    const float* y_obs  = (const float*)d_in[1];
    float* out = (float*)d_out;

    k_zero<<<1, 512>>>();
    k_sortdays<<<dim3(SGRID / K1_SER, NY), 256>>>(y_pred, y_obs);
    k_theil<<<SGRID, 192>>>();
    k_final<<<1, 1>>>(out);
}